// round 10
// baseline (speedup 1.0000x reference)
#include <cuda_runtime.h>
#include <cstdint>
#include <float.h>

// Sparsemax, one 256-thread block per row, three light passes.
//
// Pass A: stream row from DRAM, max only (4 independent fmax accumulators).
// Pass B: re-read own row (L1/L2 hit -- block streamed it microseconds ago),
//         gather candidates > rowmax-1 into smem. Hierarchical test: one
//         float4-level max-compare, descend to components only on a hit
//         (P ~ 4e-3 per float4). Support is always contained there since
//         tau >= rowmax - 1; |C| ~ 6 for Gaussian rows.
// Solve:  exact Newton/Michelot on the candidates, run redundantly by every
//         warp (no broadcast barrier).
// Pass C: last read (L1/L2 hit, evict-first) and emit max(x - tau, 0) with
//         streaming stores.
// __launch_bounds__(256, 8): regs <= 32 -> 8 blocks/SM, 100% occupancy; the
// many resident blocks mutually hide each other's serial phases.

#define COLS 8192
#define C4   (COLS / 4)
#define T    256
#define VPT  (C4 / T)             // 8 float4 per thread
#define CAP  1024                 // candidate buffer (|C| ~ 6 expected)

__global__ __launch_bounds__(T, 8)
void sparsemax3b(const float* __restrict__ x, float* __restrict__ out, int rows)
{
    __shared__ float s_red[T / 32];
    __shared__ float s_cand[CAP];
    __shared__ int   s_cnt;
    __shared__ float s_max;
    __shared__ float s_tau;
    __shared__ int   s_done;
    __shared__ float s_fb[2 * (T / 32)];

    const int tid  = threadIdx.x;
    const int lane = tid & 31;
    const int wid  = tid >> 5;
    const long long row = blockIdx.x;
    if (row >= rows) return;

    const float4* __restrict__ xr = reinterpret_cast<const float4*>(x + row * COLS);

    if (tid == 0) s_cnt = 0;

    // ---- pass A: DRAM stream, max only (4 independent chains) ----
    float m0 = -FLT_MAX, m1 = -FLT_MAX, m2 = -FLT_MAX, m3 = -FLT_MAX;
#pragma unroll
    for (int i = 0; i < VPT; ++i) {
        float4 v = xr[tid + i * T];
        m0 = fmaxf(m0, v.x);
        m1 = fmaxf(m1, v.y);
        m2 = fmaxf(m2, v.z);
        m3 = fmaxf(m3, v.w);
    }
    float m = fmaxf(fmaxf(m0, m1), fmaxf(m2, m3));
#pragma unroll
    for (int o = 16; o > 0; o >>= 1) m = fmaxf(m, __shfl_xor_sync(0xffffffffu, m, o));
    if (lane == 0) s_red[wid] = m;
    __syncthreads();                                   // also covers s_cnt init
    if (wid == 0) {
        float t = (lane < T / 32) ? s_red[lane] : -FLT_MAX;
#pragma unroll
        for (int o = 4; o > 0; o >>= 1) t = fmaxf(t, __shfl_xor_sync(0xffffffffu, t, o));
        if (lane == 0) s_max = t;
    }
    __syncthreads();
    const float thresh = s_max - 1.0f;                 // tau >= thresh always

    // ---- pass B: gather candidates > thresh (hierarchical test) ----
#pragma unroll
    for (int i = 0; i < VPT; ++i) {
        float4 v = xr[tid + i * T];
        float max4 = fmaxf(fmaxf(v.x, v.y), fmaxf(v.z, v.w));
        if (max4 > thresh) {                           // rare (~4e-3 / float4)
            if (v.x > thresh) { int q = atomicAdd(&s_cnt, 1); if (q < CAP) s_cand[q] = v.x; }
            if (v.y > thresh) { int q = atomicAdd(&s_cnt, 1); if (q < CAP) s_cand[q] = v.y; }
            if (v.z > thresh) { int q = atomicAdd(&s_cnt, 1); if (q < CAP) s_cand[q] = v.z; }
            if (v.w > thresh) { int q = atomicAdd(&s_cnt, 1); if (q < CAP) s_cand[q] = v.w; }
        }
    }
    __syncthreads();
    const int cnt = s_cnt;

    float tau;
    if (cnt <= CAP) {
        // ---- exact Newton/Michelot on tiny candidate set, ALL warps
        //      redundantly (same data -> same tau; no broadcast barrier) ----
        float tt = thresh;
#pragma unroll 1
        for (int it = 0; it < 64; ++it) {
            float s = 0.0f, k = 0.0f;
            for (int i = lane; i < cnt; i += 32) {
                float c = s_cand[i];
                if (c > tt) { s += c; k += 1.0f; }
            }
#pragma unroll
            for (int o = 16; o > 0; o >>= 1) {
                s += __shfl_xor_sync(0xffffffffu, s, o);
                k += __shfl_xor_sync(0xffffffffu, k, o);
            }
            if (k < 0.5f) break;              // safety (cannot happen in theory)
            float nt = (s - 1.0f) / k;
            if (nt == tt) break;              // exact fixed point
            tt = nt;
        }
        tau = tt;
    } else {
        // ---- pathological fallback: block Michelot over L2-resident row ----
        float tt = thresh;
#pragma unroll 1
        for (int it = 0; it < 64; ++it) {
            float s = 0.0f, k = 0.0f;
#pragma unroll 1
            for (int i = 0; i < VPT; ++i) {
                float4 v = xr[tid + i * T];
                if (v.x > tt) { s += v.x; k += 1.0f; }
                if (v.y > tt) { s += v.y; k += 1.0f; }
                if (v.z > tt) { s += v.z; k += 1.0f; }
                if (v.w > tt) { s += v.w; k += 1.0f; }
            }
#pragma unroll
            for (int o = 16; o > 0; o >>= 1) {
                s += __shfl_xor_sync(0xffffffffu, s, o);
                k += __shfl_xor_sync(0xffffffffu, k, o);
            }
            if (lane == 0) { s_fb[2 * wid] = s; s_fb[2 * wid + 1] = k; }
            __syncthreads();
            if (tid == 0) {
                float Sx = 0.0f, K = 0.0f;
                for (int w = 0; w < T / 32; ++w) { Sx += s_fb[2 * w]; K += s_fb[2 * w + 1]; }
                float nt = (K < 0.5f) ? tt : (Sx - 1.0f) / K;
                s_done = (nt == tt) || (K < 0.5f);
                s_tau  = nt;
            }
            __syncthreads();
            tt = s_tau;
            if (s_done) break;
        }
        tau = tt;
    }

    // ---- pass C: last read (L1/L2 hit, evict after), emit output ----
    float4* __restrict__ yr = reinterpret_cast<float4*>(out + row * COLS);
#pragma unroll
    for (int i = 0; i < VPT; ++i) {
        float4 v = __ldcs(xr + tid + i * T);
        float4 r;
        r.x = fmaxf(v.x - tau, 0.0f);
        r.y = fmaxf(v.y - tau, 0.0f);
        r.z = fmaxf(v.z - tau, 0.0f);
        r.w = fmaxf(v.w - tau, 0.0f);
        __stcs(yr + tid + i * T, r);
    }
}

extern "C" void kernel_launch(void* const* d_in, const int* in_sizes, int n_in,
                              void* d_out, int out_size)
{
    const float* x = (const float*)d_in[0];
    float* out     = (float*)d_out;
    const int rows = in_sizes[0] / COLS;
    sparsemax3b<<<rows, T>>>(x, out, rows);
}

// round 11
// speedup vs baseline: 1.2378x; 1.2378x over previous
#include <cuda_runtime.h>
#include <cstdint>
#include <float.h>

// Sparsemax, one 256-thread block per row, three light passes.
// == R9 configuration (regs ~40, 6 blocks/SM) + hierarchical pass-B test ==
//
// Pass A: stream row from DRAM, max only (4 independent fmax accumulators,
//         full 8-deep float4 MLP -- do NOT cap registers below this).
// Pass B: re-read own row (L1/L2 hit -- block streamed it microseconds ago),
//         gather candidates > rowmax-1 into smem. Hierarchical test: one
//         float4-level max compare, descend to components only on a hit
//         (P ~ 4e-3 per float4). Support is always contained there since
//         tau >= rowmax - 1; |C| ~ 6 for Gaussian rows.
// Solve:  exact Newton/Michelot on the candidates, run redundantly by every
//         warp (no broadcast barrier).
// Pass C: last read (L1/L2 hit, evict-first) and emit max(x - tau, 0) with
//         streaming stores.

#define COLS 8192
#define C4   (COLS / 4)
#define T    256
#define VPT  (C4 / T)             // 8 float4 per thread
#define CAP  1024                 // candidate buffer (|C| ~ 6 expected)

__global__ __launch_bounds__(T, 6)
void sparsemax3c(const float* __restrict__ x, float* __restrict__ out, int rows)
{
    __shared__ float s_red[T / 32];
    __shared__ float s_cand[CAP];
    __shared__ int   s_cnt;
    __shared__ float s_max;
    __shared__ float s_tau;
    __shared__ int   s_done;
    __shared__ float s_fb[2 * (T / 32)];

    const int tid  = threadIdx.x;
    const int lane = tid & 31;
    const int wid  = tid >> 5;
    const long long row = blockIdx.x;
    if (row >= rows) return;

    const float4* __restrict__ xr = reinterpret_cast<const float4*>(x + row * COLS);

    if (tid == 0) s_cnt = 0;

    // ---- pass A: DRAM stream, max only (4 independent chains) ----
    float m0 = -FLT_MAX, m1 = -FLT_MAX, m2 = -FLT_MAX, m3 = -FLT_MAX;
#pragma unroll
    for (int i = 0; i < VPT; ++i) {
        float4 v = xr[tid + i * T];
        m0 = fmaxf(m0, v.x);
        m1 = fmaxf(m1, v.y);
        m2 = fmaxf(m2, v.z);
        m3 = fmaxf(m3, v.w);
    }
    float m = fmaxf(fmaxf(m0, m1), fmaxf(m2, m3));
#pragma unroll
    for (int o = 16; o > 0; o >>= 1) m = fmaxf(m, __shfl_xor_sync(0xffffffffu, m, o));
    if (lane == 0) s_red[wid] = m;
    __syncthreads();                                   // also covers s_cnt init
    if (wid == 0) {
        float t = (lane < T / 32) ? s_red[lane] : -FLT_MAX;
#pragma unroll
        for (int o = 4; o > 0; o >>= 1) t = fmaxf(t, __shfl_xor_sync(0xffffffffu, t, o));
        if (lane == 0) s_max = t;
    }
    __syncthreads();
    const float thresh = s_max - 1.0f;                 // tau >= thresh always

    // ---- pass B: gather candidates > thresh (hierarchical test) ----
#pragma unroll
    for (int i = 0; i < VPT; ++i) {
        float4 v = xr[tid + i * T];
        float max4 = fmaxf(fmaxf(v.x, v.y), fmaxf(v.z, v.w));
        if (max4 > thresh) {                           // rare (~4e-3 / float4)
            if (v.x > thresh) { int q = atomicAdd(&s_cnt, 1); if (q < CAP) s_cand[q] = v.x; }
            if (v.y > thresh) { int q = atomicAdd(&s_cnt, 1); if (q < CAP) s_cand[q] = v.y; }
            if (v.z > thresh) { int q = atomicAdd(&s_cnt, 1); if (q < CAP) s_cand[q] = v.z; }
            if (v.w > thresh) { int q = atomicAdd(&s_cnt, 1); if (q < CAP) s_cand[q] = v.w; }
        }
    }
    __syncthreads();
    const int cnt = s_cnt;

    float tau;
    if (cnt <= CAP) {
        // ---- exact Newton/Michelot on tiny candidate set, ALL warps
        //      redundantly (same data -> same tau; no broadcast barrier) ----
        float tt = thresh;
#pragma unroll 1
        for (int it = 0; it < 64; ++it) {
            float s = 0.0f, k = 0.0f;
            for (int i = lane; i < cnt; i += 32) {
                float c = s_cand[i];
                if (c > tt) { s += c; k += 1.0f; }
            }
#pragma unroll
            for (int o = 16; o > 0; o >>= 1) {
                s += __shfl_xor_sync(0xffffffffu, s, o);
                k += __shfl_xor_sync(0xffffffffu, k, o);
            }
            if (k < 0.5f) break;              // safety (cannot happen in theory)
            float nt = (s - 1.0f) / k;
            if (nt == tt) break;              // exact fixed point
            tt = nt;
        }
        tau = tt;
    } else {
        // ---- pathological fallback: block Michelot over L2-resident row ----
        float tt = thresh;
#pragma unroll 1
        for (int it = 0; it < 64; ++it) {
            float s = 0.0f, k = 0.0f;
#pragma unroll 1
            for (int i = 0; i < VPT; ++i) {
                float4 v = xr[tid + i * T];
                if (v.x > tt) { s += v.x; k += 1.0f; }
                if (v.y > tt) { s += v.y; k += 1.0f; }
                if (v.z > tt) { s += v.z; k += 1.0f; }
                if (v.w > tt) { s += v.w; k += 1.0f; }
            }
#pragma unroll
            for (int o = 16; o > 0; o >>= 1) {
                s += __shfl_xor_sync(0xffffffffu, s, o);
                k += __shfl_xor_sync(0xffffffffu, k, o);
            }
            if (lane == 0) { s_fb[2 * wid] = s; s_fb[2 * wid + 1] = k; }
            __syncthreads();
            if (tid == 0) {
                float Sx = 0.0f, K = 0.0f;
                for (int w = 0; w < T / 32; ++w) { Sx += s_fb[2 * w]; K += s_fb[2 * w + 1]; }
                float nt = (K < 0.5f) ? tt : (Sx - 1.0f) / K;
                s_done = (nt == tt) || (K < 0.5f);
                s_tau  = nt;
            }
            __syncthreads();
            tt = s_tau;
            if (s_done) break;
        }
        tau = tt;
    }

    // ---- pass C: last read (L1/L2 hit, evict after), emit output ----
    float4* __restrict__ yr = reinterpret_cast<float4*>(out + row * COLS);
#pragma unroll
    for (int i = 0; i < VPT; ++i) {
        float4 v = __ldcs(xr + tid + i * T);
        float4 r;
        r.x = fmaxf(v.x - tau, 0.0f);
        r.y = fmaxf(v.y - tau, 0.0f);
        r.z = fmaxf(v.z - tau, 0.0f);
        r.w = fmaxf(v.w - tau, 0.0f);
        __stcs(yr + tid + i * T, r);
    }
}

extern "C" void kernel_launch(void* const* d_in, const int* in_sizes, int n_in,
                              void* d_out, int out_size)
{
    const float* x = (const float*)d_in[0];
    float* out     = (float*)d_out;
    const int rows = in_sizes[0] / COLS;
    sparsemax3c<<<rows, T>>>(x, out, rows);
}